// round 11
// baseline (speedup 1.0000x reference)
#include <cuda_runtime.h>
#include <math.h>

// Problem constants
#define B_  32
#define C_  512
#define T_  4000
#define NV_ 1000          // T/4 float4s
#define H4C 2048          // 4*C (stats width)
#define SP1 16            // gemm1 K-splits (K=2048, chunk 128)
#define SP2 8             // gemm2 K-splits (K=512,  chunk 64)

// ---------------- scratch (device globals; no allocation allowed) -----------
__device__ float g_statsT[H4C * B_];          // [2048][32]  feature-major, batch=lane
__device__ float g_hT[C_ * B_];               // [512][32]
__device__ float g_p1[SP1 * C_ * B_];         // gemm1 K-split partials
__device__ float g_p2[SP2 * 2 * C_ * B_];     // gemm2 K-split partials

// ---------------- kernel 1: fused add + 4-moment reduction ------------------
// All 8 LDG.128 for this thread's 4 strided iterations issued before any
// arithmetic (front-batched MLP ~ 8).
__global__ __launch_bounds__(256) void stats_kernel(
    const float* __restrict__ xa, const float* __restrict__ xb)
{
    int c = blockIdx.x;
    int b = blockIdx.y;
    size_t base = ((size_t)(b * C_ + c)) * T_;
    const float4* a4 = reinterpret_cast<const float4*>(xa + base);
    const float4* b4 = reinterpret_cast<const float4*>(xb + base);
    const int tid = threadIdx.x;

    // NV_ = 1000 = 3*256 + 232: 3 full strided iterations, 4th predicated.
    float4 av[4], bv[4];
    av[0] = a4[tid];        bv[0] = b4[tid];
    av[1] = a4[tid + 256];  bv[1] = b4[tid + 256];
    av[2] = a4[tid + 512];  bv[2] = b4[tid + 512];
    bool p3 = tid < (NV_ - 768);
    if (p3) { av[3] = a4[tid + 768]; bv[3] = b4[tid + 768]; }
    else    { av[3] = make_float4(0.f, 0.f, 0.f, 0.f);
              bv[3] = make_float4(0.f, 0.f, 0.f, 0.f); }

    float s1 = 0.f, s2 = 0.f, s3 = 0.f, s4 = 0.f;
    #pragma unroll
    for (int t = 0; t < 4; t++) {
        float xv[4] = {av[t].x + bv[t].x, av[t].y + bv[t].y,
                       av[t].z + bv[t].z, av[t].w + bv[t].w};
        #pragma unroll
        for (int q = 0; q < 4; q++) {
            float x = xv[q];
            float x2 = x * x;
            s1 += x;
            s2 = fmaf(x, x, s2);
            s3 = fmaf(x2, x, s3);
            s4 = fmaf(x2, x2, s4);
        }
    }

    #pragma unroll
    for (int off = 16; off > 0; off >>= 1) {
        s1 += __shfl_down_sync(0xffffffffu, s1, off);
        s2 += __shfl_down_sync(0xffffffffu, s2, off);
        s3 += __shfl_down_sync(0xffffffffu, s3, off);
        s4 += __shfl_down_sync(0xffffffffu, s4, off);
    }
    __shared__ float red[8][4];
    int w = tid >> 5;
    if ((tid & 31) == 0) {
        red[w][0] = s1; red[w][1] = s2; red[w][2] = s3; red[w][3] = s4;
    }
    __syncthreads();
    if (tid == 0) {
        float t1 = 0.f, t2 = 0.f, t3 = 0.f, t4 = 0.f;
        #pragma unroll
        for (int i = 0; i < 8; i++) {
            t1 += red[i][0]; t2 += red[i][1]; t3 += red[i][2]; t4 += red[i][3];
        }
        const float Tf = (float)T_;
        float m  = t1 / Tf;
        float m2 = m * m;
        float sc2 = t2 - t1 * m;                       // sum centered^2
        float var = fmaxf(sc2 / (Tf - 1.0f), 0.f);     // unbiased
        float sd  = sqrtf(var);
        float d   = fmaxf(sd, 0.01f);                  // EPS clamp
        float sc3 = t3 - 3.f * m * t2 + 2.f * Tf * m * m2;
        float sc4 = t4 - 4.f * m * t3 + 6.f * m2 * t2 - 3.f * Tf * m2 * m2;
        float d3inv = 1.f / (Tf * d * d * d);
        float skew = sc3 * d3inv;
        float kurt = sc4 * d3inv / d;
        g_statsT[(c)            * B_ + b] = m;
        g_statsT[(C_ + c)       * B_ + b] = sd;
        g_statsT[(2 * C_ + c)   * B_ + b] = skew;
        g_statsT[(3 * C_ + c)   * B_ + b] = kurt;
    }
}

// ---------------- mini-GEMM: out[r][b] partials = A[r][:K] . xT[:K][b]
// Weight tile (A) loaded into registers BEFORE cudaGridDependencySynchronize
// (PDL overlap of the cold DRAM fetch with the predecessor kernel).
template<int KC>
__device__ __forceinline__ void gemm_tile_pdl(
    const float* __restrict__ A, const float* __restrict__ xT,
    float* __restrict__ outP, int K, int rows)
{
    __shared__ __align__(16) float sA[32 * KC];   // [jj][k] row-major
    __shared__ __align__(16) float sX[KC * 32];   // [k][b]
    const int j0 = blockIdx.x * 32;
    const int i0 = blockIdx.y * KC;
    const int tid = threadIdx.x;

    constexpr int NF = KC / 32;   // float4s per thread for each tile
    float4 va[NF];
    #pragma unroll
    for (int t = 0; t < NF; t++) {
        int f  = tid + t * 256;            // f4 index in [0, 8*KC)
        int jj = f / (KC / 4);
        int kq = f % (KC / 4);
        va[t] = *reinterpret_cast<const float4*>(A + (size_t)(j0 + jj) * K + i0 + 4 * kq);
    }

    cudaGridDependencySynchronize();       // predecessor results now visible

    {
        float4 vx[NF];
        const float4* x4 = reinterpret_cast<const float4*>(xT + (size_t)i0 * B_);
        #pragma unroll
        for (int t = 0; t < NF; t++)
            vx[t] = x4[tid + t * 256];
        #pragma unroll
        for (int t = 0; t < NF; t++)
            reinterpret_cast<float4*>(sX)[tid + t * 256] = vx[t];
    }
    #pragma unroll
    for (int t = 0; t < NF; t++)
        reinterpret_cast<float4*>(sA)[tid + t * 256] = va[t];
    __syncthreads();

    const int b  = tid & 31;
    const int jb = (tid >> 5) * 4;     // 8 warps * 4 rows = 32 rows
    float a0 = 0.f, a1 = 0.f, a2 = 0.f, a3 = 0.f;
    #pragma unroll 8
    for (int k4 = 0; k4 < KC / 4; k4++) {
        float4 r0 = reinterpret_cast<const float4*>(sA)[(jb + 0) * (KC / 4) + k4];
        float4 r1 = reinterpret_cast<const float4*>(sA)[(jb + 1) * (KC / 4) + k4];
        float4 r2 = reinterpret_cast<const float4*>(sA)[(jb + 2) * (KC / 4) + k4];
        float4 r3 = reinterpret_cast<const float4*>(sA)[(jb + 3) * (KC / 4) + k4];
        float s0 = sX[(4 * k4 + 0) * 32 + b];
        float s1 = sX[(4 * k4 + 1) * 32 + b];
        float s2 = sX[(4 * k4 + 2) * 32 + b];
        float s3 = sX[(4 * k4 + 3) * 32 + b];
        a0 = fmaf(r0.x, s0, a0); a0 = fmaf(r0.y, s1, a0); a0 = fmaf(r0.z, s2, a0); a0 = fmaf(r0.w, s3, a0);
        a1 = fmaf(r1.x, s0, a1); a1 = fmaf(r1.y, s1, a1); a1 = fmaf(r1.z, s2, a1); a1 = fmaf(r1.w, s3, a1);
        a2 = fmaf(r2.x, s0, a2); a2 = fmaf(r2.y, s1, a2); a2 = fmaf(r2.z, s2, a2); a2 = fmaf(r2.w, s3, a2);
        a3 = fmaf(r3.x, s0, a3); a3 = fmaf(r3.y, s1, a3); a3 = fmaf(r3.z, s2, a3); a3 = fmaf(r3.w, s3, a3);
    }
    size_t obase = (size_t)blockIdx.y * rows * B_ + (size_t)(j0 + jb) * B_ + b;
    outP[obase + 0 * B_] = a0;
    outP[obase + 1 * B_] = a1;
    outP[obase + 2 * B_] = a2;
    outP[obase + 3 * B_] = a3;
}

__global__ __launch_bounds__(256) void gemm1_kernel(const float* __restrict__ W1)
{
    gemm_tile_pdl<128>(W1, g_statsT, g_p1, H4C, C_);
}

__global__ __launch_bounds__(256) void reduce1_kernel(const float* __restrict__ b1)
{
    int idx4 = blockIdx.x * 256 + threadIdx.x;    // over C_*B_/4 = 4096 float4s
    float bv = (idx4 < C_ * B_ / 4) ? b1[idx4 >> 3] : 0.f;   // input: safe pre-sync
    cudaGridDependencySynchronize();
    if (idx4 >= C_ * B_ / 4) return;
    float4 acc = make_float4(bv, bv, bv, bv);
    #pragma unroll
    for (int sp = 0; sp < SP1; sp++) {
        float4 p = reinterpret_cast<const float4*>(g_p1)[sp * (C_ * B_ / 4) + idx4];
        acc.x += p.x; acc.y += p.y; acc.z += p.z; acc.w += p.w;
    }
    reinterpret_cast<float4*>(g_hT)[idx4] = acc;
}

__global__ __launch_bounds__(256) void gemm2_kernel(const float* __restrict__ W2)
{
    gemm_tile_pdl<64>(W2, g_hT, g_p2, C_, 2 * C_);
}

// ---------------- kernel 5: gate reduce + softmax + weighted combine --------
// xa/xb are kernel INPUTS (not produced by predecessors): their loads are
// issued BEFORE cudaGridDependencySynchronize, so the first wave streams
// ~36MB from DRAM while the midchain kernels are still running (PDL overlap).
// Only the g_p2 gate partials are read after the sync.
__global__ __launch_bounds__(256) void apply_kernel(
    const float* __restrict__ xa, const float* __restrict__ xb,
    const float* __restrict__ b2, float* __restrict__ out)
{
    int lin = (B_ * C_ - 1) - (int)(blockIdx.y * C_ + blockIdx.x);
    int b = lin / C_;
    int c = lin - b * C_;
    const int tid = threadIdx.x;

    size_t base = ((size_t)(b * C_ + c)) * T_;
    const float4* a4 = reinterpret_cast<const float4*>(xa + base);
    const float4* b4 = reinterpret_cast<const float4*>(xb + base);
    float4* o4 = reinterpret_cast<float4*>(out + base);

    // ---- pre-sync: inputs only (xa/xb rows + bias) ----
    float s0 = b2[c];
    float s1 = b2[C_ + c];
    float4 av[4], bv[4];
    av[0] = a4[tid];        bv[0] = b4[tid];
    av[1] = a4[tid + 256];  bv[1] = b4[tid + 256];
    av[2] = a4[tid + 512];  bv[2] = b4[tid + 512];
    bool p3 = tid < (NV_ - 768);
    if (p3) { av[3] = a4[tid + 768]; bv[3] = b4[tid + 768]; }

    cudaGridDependencySynchronize();       // g_p2 now visible

    #pragma unroll
    for (int sp = 0; sp < SP2; sp++) {
        s0 += g_p2[(size_t)sp * (2 * C_ * B_) + (size_t)c * B_ + b];
        s1 += g_p2[(size_t)sp * (2 * C_ * B_) + (size_t)(C_ + c) * B_ + b];
    }
    float mx = fmaxf(s0, s1);
    float e0 = __expf(s0 - mx);
    float e1 = __expf(s1 - mx);
    float inv = 1.f / (e0 + e1);
    float g0 = e0 * inv;
    float g1 = e1 * inv;

    float4 r[4];
    #pragma unroll
    for (int t = 0; t < 4; t++) {
        r[t].x = fmaf(av[t].x, g0, bv[t].x * g1);
        r[t].y = fmaf(av[t].y, g0, bv[t].y * g1);
        r[t].z = fmaf(av[t].z, g0, bv[t].z * g1);
        r[t].w = fmaf(av[t].w, g0, bv[t].w * g1);
    }
    __stcs(&o4[tid],       r[0]);
    __stcs(&o4[tid + 256], r[1]);
    __stcs(&o4[tid + 512], r[2]);
    if (p3) __stcs(&o4[tid + 768], r[3]);
}

// ---------------- launcher --------------------------------------------------
static inline void launch_pdl(const void* fn, dim3 grid, dim3 block,
                              void** args)
{
    cudaLaunchConfig_t cfg = {};
    cfg.gridDim  = grid;
    cfg.blockDim = block;
    cfg.dynamicSmemBytes = 0;
    cfg.stream = 0;
    cudaLaunchAttribute attr[1];
    attr[0].id = cudaLaunchAttributeProgrammaticStreamSerialization;
    attr[0].val.programmaticStreamSerializationAllowed = 1;
    cfg.attrs = attr;
    cfg.numAttrs = 1;
    cudaLaunchKernelExC(&cfg, fn, args);
}

extern "C" void kernel_launch(void* const* d_in, const int* in_sizes, int n_in,
                              void* d_out, int out_size)
{
    const float* xa = (const float*)d_in[0];
    const float* xb = (const float*)d_in[1];
    const float* W1 = (const float*)d_in[2];
    const float* b1 = (const float*)d_in[3];
    const float* W2 = (const float*)d_in[4];
    const float* b2 = (const float*)d_in[5];
    float* out = (float*)d_out;

    stats_kernel<<<dim3(C_, B_), 256>>>(xa, xb);

    {   // gemm1: PDL secondary of stats (W1 preload overlaps stats tail)
        void* args[] = { (void*)&W1 };
        launch_pdl((const void*)gemm1_kernel, dim3(C_ / 32, SP1), dim3(256), args);
    }
    {   // reduce1: PDL secondary of gemm1
        void* args[] = { (void*)&b1 };
        launch_pdl((const void*)reduce1_kernel, dim3(C_ * B_ / 4 / 256), dim3(256), args);
    }
    {   // gemm2: PDL secondary of reduce1 (W2 preload overlaps)
        void* args[] = { (void*)&W2 };
        launch_pdl((const void*)gemm2_kernel, dim3(2 * C_ / 32, SP2), dim3(256), args);
    }
    {   // apply: PDL secondary of gemm2 (xa/xb first-wave loads overlap midchain)
        void* args[] = { (void*)&xa, (void*)&xb, (void*)&b2, (void*)&out };
        launch_pdl((const void*)apply_kernel, dim3(C_, B_), dim3(256), args);
    }
}

// round 12
// speedup vs baseline: 1.0013x; 1.0013x over previous
#include <cuda_runtime.h>
#include <math.h>

// Problem constants
#define B_  32
#define C_  512
#define T_  4000
#define NV_ 1000          // T/4 float4s
#define H4C 2048          // 4*C (stats width)
#define SP1 16            // gemm1 K-splits (K=2048, chunk 128)
#define SP2 8             // gemm2 K-splits (K=512,  chunk 64)

// ---------------- scratch (device globals; no allocation allowed) -----------
__device__ float g_statsT[H4C * B_];          // [2048][32]  feature-major, batch=lane
__device__ float g_p1[SP1 * C_ * B_];         // gemm1 K-split partials (1MB, L2-hot)
__device__ float g_p2[SP2 * 2 * C_ * B_];     // gemm2 K-split partials

// ---------------- kernel 1: fused add + 4-moment reduction ------------------
// All 8 LDG.128 for this thread's 4 strided iterations issued before any
// arithmetic (front-batched MLP ~ 8).
__global__ __launch_bounds__(256) void stats_kernel(
    const float* __restrict__ xa, const float* __restrict__ xb)
{
    int c = blockIdx.x;
    int b = blockIdx.y;
    size_t base = ((size_t)(b * C_ + c)) * T_;
    const float4* a4 = reinterpret_cast<const float4*>(xa + base);
    const float4* b4 = reinterpret_cast<const float4*>(xb + base);
    const int tid = threadIdx.x;

    // NV_ = 1000 = 3*256 + 232: 3 full strided iterations, 4th predicated.
    float4 av[4], bv[4];
    av[0] = a4[tid];        bv[0] = b4[tid];
    av[1] = a4[tid + 256];  bv[1] = b4[tid + 256];
    av[2] = a4[tid + 512];  bv[2] = b4[tid + 512];
    bool p3 = tid < (NV_ - 768);
    if (p3) { av[3] = a4[tid + 768]; bv[3] = b4[tid + 768]; }
    else    { av[3] = make_float4(0.f, 0.f, 0.f, 0.f);
              bv[3] = make_float4(0.f, 0.f, 0.f, 0.f); }

    float s1 = 0.f, s2 = 0.f, s3 = 0.f, s4 = 0.f;
    #pragma unroll
    for (int t = 0; t < 4; t++) {
        float xv[4] = {av[t].x + bv[t].x, av[t].y + bv[t].y,
                       av[t].z + bv[t].z, av[t].w + bv[t].w};
        #pragma unroll
        for (int q = 0; q < 4; q++) {
            float x = xv[q];
            float x2 = x * x;
            s1 += x;
            s2 = fmaf(x, x, s2);
            s3 = fmaf(x2, x, s3);
            s4 = fmaf(x2, x2, s4);
        }
    }

    #pragma unroll
    for (int off = 16; off > 0; off >>= 1) {
        s1 += __shfl_down_sync(0xffffffffu, s1, off);
        s2 += __shfl_down_sync(0xffffffffu, s2, off);
        s3 += __shfl_down_sync(0xffffffffu, s3, off);
        s4 += __shfl_down_sync(0xffffffffu, s4, off);
    }
    __shared__ float red[8][4];
    int w = tid >> 5;
    if ((tid & 31) == 0) {
        red[w][0] = s1; red[w][1] = s2; red[w][2] = s3; red[w][3] = s4;
    }
    __syncthreads();
    if (tid == 0) {
        float t1 = 0.f, t2 = 0.f, t3 = 0.f, t4 = 0.f;
        #pragma unroll
        for (int i = 0; i < 8; i++) {
            t1 += red[i][0]; t2 += red[i][1]; t3 += red[i][2]; t4 += red[i][3];
        }
        const float Tf = (float)T_;
        float m  = t1 / Tf;
        float m2 = m * m;
        float sc2 = t2 - t1 * m;                       // sum centered^2
        float var = fmaxf(sc2 / (Tf - 1.0f), 0.f);     // unbiased
        float sd  = sqrtf(var);
        float d   = fmaxf(sd, 0.01f);                  // EPS clamp
        float sc3 = t3 - 3.f * m * t2 + 2.f * Tf * m * m2;
        float sc4 = t4 - 4.f * m * t3 + 6.f * m2 * t2 - 3.f * Tf * m2 * m2;
        float d3inv = 1.f / (Tf * d * d * d);
        float skew = sc3 * d3inv;
        float kurt = sc4 * d3inv / d;
        g_statsT[(c)            * B_ + b] = m;
        g_statsT[(C_ + c)       * B_ + b] = sd;
        g_statsT[(2 * C_ + c)   * B_ + b] = skew;
        g_statsT[(3 * C_ + c)   * B_ + b] = kurt;
    }
}

// ---------------- gemm1: h partials = W1 . statsT, K-split 16 ---------------
// W1 tile loaded into registers BEFORE cudaGridDependencySynchronize (PDL
// overlap of the cold DRAM fetch with the stats kernel's tail).
__global__ __launch_bounds__(256) void gemm1_kernel(const float* __restrict__ W1)
{
    constexpr int KC = 128;
    __shared__ __align__(16) float sA[32 * KC];   // [jj][k] row-major
    __shared__ __align__(16) float sX[KC * 32];   // [k][b]
    const int j0 = blockIdx.x * 32;
    const int i0 = blockIdx.y * KC;
    const int tid = threadIdx.x;

    constexpr int NF = KC / 32;   // 4 float4s per thread per tile
    float4 va[NF];
    #pragma unroll
    for (int t = 0; t < NF; t++) {
        int f  = tid + t * 256;
        int jj = f / (KC / 4);
        int kq = f % (KC / 4);
        va[t] = *reinterpret_cast<const float4*>(W1 + (size_t)(j0 + jj) * H4C + i0 + 4 * kq);
    }

    cudaGridDependencySynchronize();       // statsT now visible

    {
        float4 vx[NF];
        const float4* x4 = reinterpret_cast<const float4*>(g_statsT + (size_t)i0 * B_);
        #pragma unroll
        for (int t = 0; t < NF; t++)
            vx[t] = x4[tid + t * 256];
        #pragma unroll
        for (int t = 0; t < NF; t++)
            reinterpret_cast<float4*>(sX)[tid + t * 256] = vx[t];
    }
    #pragma unroll
    for (int t = 0; t < NF; t++)
        reinterpret_cast<float4*>(sA)[tid + t * 256] = va[t];
    __syncthreads();

    const int b  = tid & 31;
    const int jb = (tid >> 5) * 4;     // 8 warps * 4 rows = 32 rows
    float a0 = 0.f, a1 = 0.f, a2 = 0.f, a3 = 0.f;
    #pragma unroll 8
    for (int k4 = 0; k4 < KC / 4; k4++) {
        float4 r0 = reinterpret_cast<const float4*>(sA)[(jb + 0) * (KC / 4) + k4];
        float4 r1 = reinterpret_cast<const float4*>(sA)[(jb + 1) * (KC / 4) + k4];
        float4 r2 = reinterpret_cast<const float4*>(sA)[(jb + 2) * (KC / 4) + k4];
        float4 r3 = reinterpret_cast<const float4*>(sA)[(jb + 3) * (KC / 4) + k4];
        float s0 = sX[(4 * k4 + 0) * 32 + b];
        float s1 = sX[(4 * k4 + 1) * 32 + b];
        float s2 = sX[(4 * k4 + 2) * 32 + b];
        float s3 = sX[(4 * k4 + 3) * 32 + b];
        a0 = fmaf(r0.x, s0, a0); a0 = fmaf(r0.y, s1, a0); a0 = fmaf(r0.z, s2, a0); a0 = fmaf(r0.w, s3, a0);
        a1 = fmaf(r1.x, s0, a1); a1 = fmaf(r1.y, s1, a1); a1 = fmaf(r1.z, s2, a1); a1 = fmaf(r1.w, s3, a1);
        a2 = fmaf(r2.x, s0, a2); a2 = fmaf(r2.y, s1, a2); a2 = fmaf(r2.z, s2, a2); a2 = fmaf(r2.w, s3, a2);
        a3 = fmaf(r3.x, s0, a3); a3 = fmaf(r3.y, s1, a3); a3 = fmaf(r3.z, s2, a3); a3 = fmaf(r3.w, s3, a3);
    }
    size_t obase = (size_t)blockIdx.y * C_ * B_ + (size_t)(j0 + jb) * B_ + b;
    g_p1[obase + 0 * B_] = a0;
    g_p1[obase + 1 * B_] = a1;
    g_p1[obase + 2 * B_] = a2;
    g_p1[obase + 3 * B_] = a3;
}

// ---------------- gemm2r: fused (reduce g_p1 + bias) + gate GEMM ------------
// Each block reduces the 64-row hT chunk it needs directly from g_p1 (L2-hot,
// fixed sp order -> deterministic), eliminating the reduce1 kernel. W2 tile
// preloads pre-sync, overlapping gemm1's whole execution.
__global__ __launch_bounds__(256) void gemm2r_kernel(
    const float* __restrict__ W2, const float* __restrict__ b1)
{
    constexpr int KC = 64;
    __shared__ __align__(16) float sA[32 * KC];   // [jj][k] W2 tile
    __shared__ __align__(16) float sX[KC * 32];   // [k][b]  reduced hT chunk
    const int j0 = blockIdx.x * 32;   // 32 jtiles over 2C rows
    const int i0 = blockIdx.y * KC;   // 8 k-chunks of 64
    const int tid = threadIdx.x;

    // pre-sync: W2 tile (input, independent of predecessors)
    float4 va[2];
    #pragma unroll
    for (int t = 0; t < 2; t++) {
        int f  = tid + t * 256;          // [0,512)
        int jj = f / 16;                 // 64/4 f4 per row
        int kq = f % 16;
        va[t] = *reinterpret_cast<const float4*>(W2 + (size_t)(j0 + jj) * C_ + i0 + 4 * kq);
    }
    // bias for the two hT f4-chunks this thread reduces
    float bb[2];
    bb[0] = b1[i0 + (tid >> 3)];
    bb[1] = b1[i0 + ((tid + 256) >> 3)];

    cudaGridDependencySynchronize();     // g_p1 now visible

    // reduce hT chunk [i0:i0+64][0:32] from g_p1 (16 splits, fixed order)
    #pragma unroll
    for (int t = 0; t < 2; t++) {
        int l = tid + t * 256;           // f4 index within chunk, [0,512)
        int base4 = i0 * (B_ / 4) + l;   // f4 index within one split of g_p1
        float4 acc = make_float4(bb[t], bb[t], bb[t], bb[t]);
        #pragma unroll
        for (int sp = 0; sp < SP1; sp++) {
            float4 p = reinterpret_cast<const float4*>(g_p1)[sp * (C_ * B_ / 4) + base4];
            acc.x += p.x; acc.y += p.y; acc.z += p.z; acc.w += p.w;
        }
        reinterpret_cast<float4*>(sX)[l] = acc;
    }
    #pragma unroll
    for (int t = 0; t < 2; t++)
        reinterpret_cast<float4*>(sA)[tid + t * 256] = va[t];
    __syncthreads();

    const int b  = tid & 31;
    const int jb = (tid >> 5) * 4;
    float a0 = 0.f, a1 = 0.f, a2 = 0.f, a3 = 0.f;
    #pragma unroll 8
    for (int k4 = 0; k4 < KC / 4; k4++) {
        float4 r0 = reinterpret_cast<const float4*>(sA)[(jb + 0) * (KC / 4) + k4];
        float4 r1 = reinterpret_cast<const float4*>(sA)[(jb + 1) * (KC / 4) + k4];
        float4 r2 = reinterpret_cast<const float4*>(sA)[(jb + 2) * (KC / 4) + k4];
        float4 r3 = reinterpret_cast<const float4*>(sA)[(jb + 3) * (KC / 4) + k4];
        float s0 = sX[(4 * k4 + 0) * 32 + b];
        float s1 = sX[(4 * k4 + 1) * 32 + b];
        float s2 = sX[(4 * k4 + 2) * 32 + b];
        float s3 = sX[(4 * k4 + 3) * 32 + b];
        a0 = fmaf(r0.x, s0, a0); a0 = fmaf(r0.y, s1, a0); a0 = fmaf(r0.z, s2, a0); a0 = fmaf(r0.w, s3, a0);
        a1 = fmaf(r1.x, s0, a1); a1 = fmaf(r1.y, s1, a1); a1 = fmaf(r1.z, s2, a1); a1 = fmaf(r1.w, s3, a1);
        a2 = fmaf(r2.x, s0, a2); a2 = fmaf(r2.y, s1, a2); a2 = fmaf(r2.z, s2, a2); a2 = fmaf(r2.w, s3, a2);
        a3 = fmaf(r3.x, s0, a3); a3 = fmaf(r3.y, s1, a3); a3 = fmaf(r3.z, s2, a3); a3 = fmaf(r3.w, s3, a3);
    }
    size_t obase = (size_t)blockIdx.y * (2 * C_) * B_ + (size_t)(j0 + jb) * B_ + b;
    g_p2[obase + 0 * B_] = a0;
    g_p2[obase + 1 * B_] = a1;
    g_p2[obase + 2 * B_] = a2;
    g_p2[obase + 3 * B_] = a3;
}

// ---------------- kernel 4: gate reduce + softmax + weighted combine --------
// Front-batched loads (8 LDG.128) after the dependency sync, 4 streaming stores.
__global__ __launch_bounds__(256) void apply_kernel(
    const float* __restrict__ xa, const float* __restrict__ xb,
    const float* __restrict__ b2, float* __restrict__ out)
{
    int lin = (B_ * C_ - 1) - (int)(blockIdx.y * C_ + blockIdx.x);
    int b = lin / C_;
    int c = lin - b * C_;

    // inputs independent of predecessors: read before sync
    float s0 = b2[c];
    float s1 = b2[C_ + c];

    cudaGridDependencySynchronize();       // g_p2 now visible

    #pragma unroll
    for (int sp = 0; sp < SP2; sp++) {
        s0 += g_p2[(size_t)sp * (2 * C_ * B_) + (size_t)c * B_ + b];
        s1 += g_p2[(size_t)sp * (2 * C_ * B_) + (size_t)(C_ + c) * B_ + b];
    }
    float mx = fmaxf(s0, s1);
    float e0 = __expf(s0 - mx);
    float e1 = __expf(s1 - mx);
    float inv = 1.f / (e0 + e1);
    float g0 = e0 * inv;
    float g1 = e1 * inv;

    size_t base = ((size_t)(b * C_ + c)) * T_;
    const float4* a4 = reinterpret_cast<const float4*>(xa + base);
    const float4* b4 = reinterpret_cast<const float4*>(xb + base);
    float4* o4 = reinterpret_cast<float4*>(out + base);
    const int tid = threadIdx.x;

    float4 av[4], bv[4];
    av[0] = a4[tid];        bv[0] = b4[tid];
    av[1] = a4[tid + 256];  bv[1] = b4[tid + 256];
    av[2] = a4[tid + 512];  bv[2] = b4[tid + 512];
    bool p3 = tid < (NV_ - 768);
    if (p3) { av[3] = a4[tid + 768]; bv[3] = b4[tid + 768]; }

    float4 r[4];
    #pragma unroll
    for (int t = 0; t < 4; t++) {
        r[t].x = fmaf(av[t].x, g0, bv[t].x * g1);
        r[t].y = fmaf(av[t].y, g0, bv[t].y * g1);
        r[t].z = fmaf(av[t].z, g0, bv[t].z * g1);
        r[t].w = fmaf(av[t].w, g0, bv[t].w * g1);
    }
    __stcs(&o4[tid],       r[0]);
    __stcs(&o4[tid + 256], r[1]);
    __stcs(&o4[tid + 512], r[2]);
    if (p3) __stcs(&o4[tid + 768], r[3]);
}

// ---------------- launcher --------------------------------------------------
static inline void launch_pdl(const void* fn, dim3 grid, dim3 block,
                              void** args)
{
    cudaLaunchConfig_t cfg = {};
    cfg.gridDim  = grid;
    cfg.blockDim = block;
    cfg.dynamicSmemBytes = 0;
    cfg.stream = 0;
    cudaLaunchAttribute attr[1];
    attr[0].id = cudaLaunchAttributeProgrammaticStreamSerialization;
    attr[0].val.programmaticStreamSerializationAllowed = 1;
    cfg.attrs = attr;
    cfg.numAttrs = 1;
    cudaLaunchKernelExC(&cfg, fn, args);
}

extern "C" void kernel_launch(void* const* d_in, const int* in_sizes, int n_in,
                              void* d_out, int out_size)
{
    const float* xa = (const float*)d_in[0];
    const float* xb = (const float*)d_in[1];
    const float* W1 = (const float*)d_in[2];
    const float* b1 = (const float*)d_in[3];
    const float* W2 = (const float*)d_in[4];
    const float* b2 = (const float*)d_in[5];
    float* out = (float*)d_out;

    stats_kernel<<<dim3(C_, B_), 256>>>(xa, xb);

    {   // gemm1: PDL secondary of stats (W1 preload overlaps stats tail)
        void* args[] = { (void*)&W1 };
        launch_pdl((const void*)gemm1_kernel, dim3(C_ / 32, SP1), dim3(256), args);
    }
    {   // gemm2r: PDL secondary of gemm1 (W2 preload overlaps all of gemm1;
        // does its own g_p1 reduction -> reduce1 kernel eliminated)
        void* args[] = { (void*)&W2, (void*)&b1 };
        launch_pdl((const void*)gemm2r_kernel, dim3(2 * C_ / 32, SP2), dim3(256), args);
    }
    {   // apply: PDL secondary of gemm2r
        void* args[] = { (void*)&xa, (void*)&xb, (void*)&b2, (void*)&out };
        launch_pdl((const void*)apply_kernel, dim3(C_, B_), dim3(256), args);
    }
}

// round 14
// speedup vs baseline: 1.0070x; 1.0056x over previous
#include <cuda_runtime.h>
#include <math.h>

// Problem constants
#define B_  32
#define C_  512
#define T_  4000
#define NV_ 1000          // T/4 float4s
#define H4C 2048          // 4*C (stats width)
#define SP1 16            // gemm1 K-splits (K=2048, chunk 128)
#define SP2 8             // gemm2 K-splits (K=512,  chunk 64)

// ---------------- scratch (device globals; no allocation allowed) -----------
__device__ float g_statsT[H4C * B_];          // [2048][32]  feature-major, batch=lane
__device__ float g_hT[C_ * B_];               // [512][32]
__device__ float g_p1[SP1 * C_ * B_];         // gemm1 K-split partials
__device__ float g_p2[SP2 * 2 * C_ * B_];     // gemm2 K-split partials

// ---------------- moments helper: accumulate + block-reduce + finalize ------
__device__ __forceinline__ void moments_reduce_store(
    const float4 av[4], const float4 bv[4], int c, int b, float (*red)[4])
{
    const int tid = threadIdx.x;
    float s1 = 0.f, s2 = 0.f, s3 = 0.f, s4 = 0.f;
    #pragma unroll
    for (int t = 0; t < 4; t++) {
        float xv[4] = {av[t].x + bv[t].x, av[t].y + bv[t].y,
                       av[t].z + bv[t].z, av[t].w + bv[t].w};
        #pragma unroll
        for (int q = 0; q < 4; q++) {
            float x = xv[q];
            float x2 = x * x;
            s1 += x;
            s2 = fmaf(x, x, s2);
            s3 = fmaf(x2, x, s3);
            s4 = fmaf(x2, x2, s4);
        }
    }
    #pragma unroll
    for (int off = 16; off > 0; off >>= 1) {
        s1 += __shfl_down_sync(0xffffffffu, s1, off);
        s2 += __shfl_down_sync(0xffffffffu, s2, off);
        s3 += __shfl_down_sync(0xffffffffu, s3, off);
        s4 += __shfl_down_sync(0xffffffffu, s4, off);
    }
    int w = tid >> 5;
    if ((tid & 31) == 0) {
        red[w][0] = s1; red[w][1] = s2; red[w][2] = s3; red[w][3] = s4;
    }
    __syncthreads();
    if (tid == 0) {
        float t1 = 0.f, t2 = 0.f, t3 = 0.f, t4 = 0.f;
        #pragma unroll
        for (int i = 0; i < 8; i++) {
            t1 += red[i][0]; t2 += red[i][1]; t3 += red[i][2]; t4 += red[i][3];
        }
        const float Tf = (float)T_;
        float m  = t1 / Tf;
        float m2 = m * m;
        float sc2 = t2 - t1 * m;                       // sum centered^2
        float var = fmaxf(sc2 / (Tf - 1.0f), 0.f);     // unbiased
        float sd  = sqrtf(var);
        float d   = fmaxf(sd, 0.01f);                  // EPS clamp
        float sc3 = t3 - 3.f * m * t2 + 2.f * Tf * m * m2;
        float sc4 = t4 - 4.f * m * t3 + 6.f * m2 * t2 - 3.f * Tf * m2 * m2;
        float d3inv = 1.f / (Tf * d * d * d);
        float skew = sc3 * d3inv;
        float kurt = sc4 * d3inv / d;
        g_statsT[(c)            * B_ + b] = m;
        g_statsT[(C_ + c)       * B_ + b] = sd;
        g_statsT[(2 * C_ + c)   * B_ + b] = skew;
        g_statsT[(3 * C_ + c)   * B_ + b] = kurt;
    }
    __syncthreads();   // red[] reused by the second row
}

// ---------------- kernel 1: fused add + 4-moment reduction, 2 rows/block ----
// ALL 16 LDG.128 (both rows) issued before any arithmetic: row B's loads are
// in flight through row A's compute + reduction tail -> no DRAM bubble at the
// reduction barrier.
__global__ __launch_bounds__(256) void stats_kernel(
    const float* __restrict__ xa, const float* __restrict__ xb)
{
    int c  = blockIdx.x;
    int b0 = blockIdx.y;            // rows (c,b0) and (c,b0+16)
    int b1 = b0 + B_ / 2;
    const int tid = threadIdx.x;
    size_t baseA = ((size_t)(b0 * C_ + c)) * T_;
    size_t baseB = ((size_t)(b1 * C_ + c)) * T_;
    const float4* aA = reinterpret_cast<const float4*>(xa + baseA);
    const float4* bA = reinterpret_cast<const float4*>(xb + baseA);
    const float4* aB = reinterpret_cast<const float4*>(xa + baseB);
    const float4* bB = reinterpret_cast<const float4*>(xb + baseB);

    bool p3 = tid < (NV_ - 768);
    float4 avA[4], bvA[4], avB[4], bvB[4];
    // front-batched: 16 LDG.128
    avA[0] = aA[tid];        bvA[0] = bA[tid];
    avA[1] = aA[tid + 256];  bvA[1] = bA[tid + 256];
    avA[2] = aA[tid + 512];  bvA[2] = bA[tid + 512];
    avB[0] = aB[tid];        bvB[0] = bB[tid];
    avB[1] = aB[tid + 256];  bvB[1] = bB[tid + 256];
    avB[2] = aB[tid + 512];  bvB[2] = bB[tid + 512];
    if (p3) {
        avA[3] = aA[tid + 768]; bvA[3] = bA[tid + 768];
        avB[3] = aB[tid + 768]; bvB[3] = bB[tid + 768];
    } else {
        float4 z = make_float4(0.f, 0.f, 0.f, 0.f);
        avA[3] = z; bvA[3] = z; avB[3] = z; bvB[3] = z;
    }

    __shared__ float red[8][4];
    moments_reduce_store(avA, bvA, c, b0, red);   // row B loads still in flight
    moments_reduce_store(avB, bvB, c, b1, red);
}

// ---------------- mini-GEMM: out[r][b] partials = A[r][:K] . xT[:K][b]
// Weight tile (A) loaded into registers BEFORE cudaGridDependencySynchronize
// (PDL overlap of the cold DRAM fetch with the predecessor kernel).
template<int KC>
__device__ __forceinline__ void gemm_tile_pdl(
    const float* __restrict__ A, const float* __restrict__ xT,
    float* __restrict__ outP, int K, int rows)
{
    __shared__ __align__(16) float sA[32 * KC];   // [jj][k] row-major
    __shared__ __align__(16) float sX[KC * 32];   // [k][b]
    const int j0 = blockIdx.x * 32;
    const int i0 = blockIdx.y * KC;
    const int tid = threadIdx.x;

    constexpr int NF = KC / 32;   // float4s per thread for each tile
    float4 va[NF];
    #pragma unroll
    for (int t = 0; t < NF; t++) {
        int f  = tid + t * 256;            // f4 index in [0, 8*KC)
        int jj = f / (KC / 4);
        int kq = f % (KC / 4);
        va[t] = *reinterpret_cast<const float4*>(A + (size_t)(j0 + jj) * K + i0 + 4 * kq);
    }

    cudaGridDependencySynchronize();       // predecessor results now visible

    {
        float4 vx[NF];
        const float4* x4 = reinterpret_cast<const float4*>(xT + (size_t)i0 * B_);
        #pragma unroll
        for (int t = 0; t < NF; t++)
            vx[t] = x4[tid + t * 256];
        #pragma unroll
        for (int t = 0; t < NF; t++)
            reinterpret_cast<float4*>(sX)[tid + t * 256] = vx[t];
    }
    #pragma unroll
    for (int t = 0; t < NF; t++)
        reinterpret_cast<float4*>(sA)[tid + t * 256] = va[t];
    __syncthreads();

    const int b  = tid & 31;
    const int jb = (tid >> 5) * 4;     // 8 warps * 4 rows = 32 rows
    float a0 = 0.f, a1 = 0.f, a2 = 0.f, a3 = 0.f;
    #pragma unroll 8
    for (int k4 = 0; k4 < KC / 4; k4++) {
        float4 r0 = reinterpret_cast<const float4*>(sA)[(jb + 0) * (KC / 4) + k4];
        float4 r1 = reinterpret_cast<const float4*>(sA)[(jb + 1) * (KC / 4) + k4];
        float4 r2 = reinterpret_cast<const float4*>(sA)[(jb + 2) * (KC / 4) + k4];
        float4 r3 = reinterpret_cast<const float4*>(sA)[(jb + 3) * (KC / 4) + k4];
        float s0 = sX[(4 * k4 + 0) * 32 + b];
        float s1 = sX[(4 * k4 + 1) * 32 + b];
        float s2 = sX[(4 * k4 + 2) * 32 + b];
        float s3 = sX[(4 * k4 + 3) * 32 + b];
        a0 = fmaf(r0.x, s0, a0); a0 = fmaf(r0.y, s1, a0); a0 = fmaf(r0.z, s2, a0); a0 = fmaf(r0.w, s3, a0);
        a1 = fmaf(r1.x, s0, a1); a1 = fmaf(r1.y, s1, a1); a1 = fmaf(r1.z, s2, a1); a1 = fmaf(r1.w, s3, a1);
        a2 = fmaf(r2.x, s0, a2); a2 = fmaf(r2.y, s1, a2); a2 = fmaf(r2.z, s2, a2); a2 = fmaf(r2.w, s3, a2);
        a3 = fmaf(r3.x, s0, a3); a3 = fmaf(r3.y, s1, a3); a3 = fmaf(r3.z, s2, a3); a3 = fmaf(r3.w, s3, a3);
    }
    size_t obase = (size_t)blockIdx.y * rows * B_ + (size_t)(j0 + jb) * B_ + b;
    outP[obase + 0 * B_] = a0;
    outP[obase + 1 * B_] = a1;
    outP[obase + 2 * B_] = a2;
    outP[obase + 3 * B_] = a3;
}

__global__ __launch_bounds__(256) void gemm1_kernel(const float* __restrict__ W1)
{
    gemm_tile_pdl<128>(W1, g_statsT, g_p1, H4C, C_);
}

__global__ __launch_bounds__(256) void reduce1_kernel(const float* __restrict__ b1)
{
    int idx4 = blockIdx.x * 256 + threadIdx.x;    // over C_*B_/4 = 4096 float4s
    float bv = (idx4 < C_ * B_ / 4) ? b1[idx4 >> 3] : 0.f;   // input: safe pre-sync
    cudaGridDependencySynchronize();
    if (idx4 >= C_ * B_ / 4) return;
    float4 acc = make_float4(bv, bv, bv, bv);
    #pragma unroll
    for (int sp = 0; sp < SP1; sp++) {
        float4 p = reinterpret_cast<const float4*>(g_p1)[sp * (C_ * B_ / 4) + idx4];
        acc.x += p.x; acc.y += p.y; acc.z += p.z; acc.w += p.w;
    }
    reinterpret_cast<float4*>(g_hT)[idx4] = acc;
}

__global__ __launch_bounds__(256) void gemm2_kernel(const float* __restrict__ W2)
{
    gemm_tile_pdl<64>(W2, g_hT, g_p2, C_, 2 * C_);
}

// ---------------- kernel 5: gate reduce + softmax + weighted combine --------
// Front-batched loads (8 LDG.128) after the dependency sync, 4 streaming stores.
__global__ __launch_bounds__(256) void apply_kernel(
    const float* __restrict__ xa, const float* __restrict__ xb,
    const float* __restrict__ b2, float* __restrict__ out)
{
    int lin = (B_ * C_ - 1) - (int)(blockIdx.y * C_ + blockIdx.x);
    int b = lin / C_;
    int c = lin - b * C_;

    // inputs independent of predecessors: read before sync
    float s0 = b2[c];
    float s1 = b2[C_ + c];

    cudaGridDependencySynchronize();       // g_p2 now visible

    #pragma unroll
    for (int sp = 0; sp < SP2; sp++) {
        s0 += g_p2[(size_t)sp * (2 * C_ * B_) + (size_t)c * B_ + b];
        s1 += g_p2[(size_t)sp * (2 * C_ * B_) + (size_t)(C_ + c) * B_ + b];
    }
    float mx = fmaxf(s0, s1);
    float e0 = __expf(s0 - mx);
    float e1 = __expf(s1 - mx);
    float inv = 1.f / (e0 + e1);
    float g0 = e0 * inv;
    float g1 = e1 * inv;

    size_t base = ((size_t)(b * C_ + c)) * T_;
    const float4* a4 = reinterpret_cast<const float4*>(xa + base);
    const float4* b4 = reinterpret_cast<const float4*>(xb + base);
    float4* o4 = reinterpret_cast<float4*>(out + base);
    const int tid = threadIdx.x;

    float4 av[4], bv[4];
    av[0] = a4[tid];        bv[0] = b4[tid];
    av[1] = a4[tid + 256];  bv[1] = b4[tid + 256];
    av[2] = a4[tid + 512];  bv[2] = b4[tid + 512];
    bool p3 = tid < (NV_ - 768);
    if (p3) { av[3] = a4[tid + 768]; bv[3] = b4[tid + 768]; }

    float4 r[4];
    #pragma unroll
    for (int t = 0; t < 4; t++) {
        r[t].x = fmaf(av[t].x, g0, bv[t].x * g1);
        r[t].y = fmaf(av[t].y, g0, bv[t].y * g1);
        r[t].z = fmaf(av[t].z, g0, bv[t].z * g1);
        r[t].w = fmaf(av[t].w, g0, bv[t].w * g1);
    }
    __stcs(&o4[tid],       r[0]);
    __stcs(&o4[tid + 256], r[1]);
    __stcs(&o4[tid + 512], r[2]);
    if (p3) __stcs(&o4[tid + 768], r[3]);
}

// ---------------- launcher --------------------------------------------------
static inline void launch_pdl(const void* fn, dim3 grid, dim3 block,
                              void** args)
{
    cudaLaunchConfig_t cfg = {};
    cfg.gridDim  = grid;
    cfg.blockDim = block;
    cfg.dynamicSmemBytes = 0;
    cfg.stream = 0;
    cudaLaunchAttribute attr[1];
    attr[0].id = cudaLaunchAttributeProgrammaticStreamSerialization;
    attr[0].val.programmaticStreamSerializationAllowed = 1;
    cfg.attrs = attr;
    cfg.numAttrs = 1;
    cudaLaunchKernelExC(&cfg, fn, args);
}

extern "C" void kernel_launch(void* const* d_in, const int* in_sizes, int n_in,
                              void* d_out, int out_size)
{
    const float* xa = (const float*)d_in[0];
    const float* xb = (const float*)d_in[1];
    const float* W1 = (const float*)d_in[2];
    const float* b1 = (const float*)d_in[3];
    const float* W2 = (const float*)d_in[4];
    const float* b2 = (const float*)d_in[5];
    float* out = (float*)d_out;

    stats_kernel<<<dim3(C_, B_ / 2), 256>>>(xa, xb);

    {   // gemm1: PDL secondary of stats (W1 preload overlaps stats tail)
        void* args[] = { (void*)&W1 };
        launch_pdl((const void*)gemm1_kernel, dim3(C_ / 32, SP1), dim3(256), args);
    }
    {   // reduce1: PDL secondary of gemm1
        void* args[] = { (void*)&b1 };
        launch_pdl((const void*)reduce1_kernel, dim3(C_ * B_ / 4 / 256), dim3(256), args);
    }
    {   // gemm2: PDL secondary of reduce1 (W2 preload overlaps)
        void* args[] = { (void*)&W2 };
        launch_pdl((const void*)gemm2_kernel, dim3(2 * C_ / 32, SP2), dim3(256), args);
    }
    {   // apply: PDL secondary of gemm2
        void* args[] = { (void*)&xa, (void*)&xb, (void*)&b2, (void*)&out };
        launch_pdl((const void*)apply_kernel, dim3(C_, B_), dim3(256), args);
    }
}

// round 17
// speedup vs baseline: 1.0200x; 1.0129x over previous
#include <cuda_runtime.h>
#include <math.h>

// Problem constants
#define B_  32
#define C_  512
#define T_  4000
#define NV_ 1000          // T/4 float4s
#define H4C 2048          // 4*C (stats width)
#define SP1 16            // gemm1 K-splits (K=2048, chunk 128)

// ---------------- scratch (device globals; no allocation allowed) -----------
__device__ float g_statsT[H4C * B_];          // [2048][32]  feature-major, batch=lane
__device__ float g_hT[C_ * B_];               // [512][32]   (k-major, for debug/reuse)
__device__ float g_hTt[B_ * C_];              // [32][512]   batch-major for apply
__device__ float g_p1[SP1 * C_ * B_];         // gemm1 K-split partials

// ---------------- kernel 1: fused add + 4-moment reduction ------------------
// All 8 LDG.128 for this thread's 4 strided iterations issued before any
// arithmetic (front-batched MLP ~ 8).
__global__ __launch_bounds__(256) void stats_kernel(
    const float* __restrict__ xa, const float* __restrict__ xb)
{
    int c = blockIdx.x;
    int b = blockIdx.y;
    size_t base = ((size_t)(b * C_ + c)) * T_;
    const float4* a4 = reinterpret_cast<const float4*>(xa + base);
    const float4* b4 = reinterpret_cast<const float4*>(xb + base);
    const int tid = threadIdx.x;

    // NV_ = 1000 = 3*256 + 232: 3 full strided iterations, 4th predicated.
    float4 av[4], bv[4];
    av[0] = a4[tid];        bv[0] = b4[tid];
    av[1] = a4[tid + 256];  bv[1] = b4[tid + 256];
    av[2] = a4[tid + 512];  bv[2] = b4[tid + 512];
    bool p3 = tid < (NV_ - 768);
    if (p3) { av[3] = a4[tid + 768]; bv[3] = b4[tid + 768]; }
    else    { av[3] = make_float4(0.f, 0.f, 0.f, 0.f);
              bv[3] = make_float4(0.f, 0.f, 0.f, 0.f); }

    float s1 = 0.f, s2 = 0.f, s3 = 0.f, s4 = 0.f;
    #pragma unroll
    for (int t = 0; t < 4; t++) {
        float xv[4] = {av[t].x + bv[t].x, av[t].y + bv[t].y,
                       av[t].z + bv[t].z, av[t].w + bv[t].w};
        #pragma unroll
        for (int q = 0; q < 4; q++) {
            float x = xv[q];
            float x2 = x * x;
            s1 += x;
            s2 = fmaf(x, x, s2);
            s3 = fmaf(x2, x, s3);
            s4 = fmaf(x2, x2, s4);
        }
    }

    #pragma unroll
    for (int off = 16; off > 0; off >>= 1) {
        s1 += __shfl_down_sync(0xffffffffu, s1, off);
        s2 += __shfl_down_sync(0xffffffffu, s2, off);
        s3 += __shfl_down_sync(0xffffffffu, s3, off);
        s4 += __shfl_down_sync(0xffffffffu, s4, off);
    }
    __shared__ float red[8][4];
    int w = tid >> 5;
    if ((tid & 31) == 0) {
        red[w][0] = s1; red[w][1] = s2; red[w][2] = s3; red[w][3] = s4;
    }
    __syncthreads();
    if (tid == 0) {
        float t1 = 0.f, t2 = 0.f, t3 = 0.f, t4 = 0.f;
        #pragma unroll
        for (int i = 0; i < 8; i++) {
            t1 += red[i][0]; t2 += red[i][1]; t3 += red[i][2]; t4 += red[i][3];
        }
        const float Tf = (float)T_;
        float m  = t1 / Tf;
        float m2 = m * m;
        float sc2 = t2 - t1 * m;                       // sum centered^2
        float var = fmaxf(sc2 / (Tf - 1.0f), 0.f);     // unbiased
        float sd  = sqrtf(var);
        float d   = fmaxf(sd, 0.01f);                  // EPS clamp
        float sc3 = t3 - 3.f * m * t2 + 2.f * Tf * m * m2;
        float sc4 = t4 - 4.f * m * t3 + 6.f * m2 * t2 - 3.f * Tf * m2 * m2;
        float d3inv = 1.f / (Tf * d * d * d);
        float skew = sc3 * d3inv;
        float kurt = sc4 * d3inv / d;
        g_statsT[(c)            * B_ + b] = m;
        g_statsT[(C_ + c)       * B_ + b] = sd;
        g_statsT[(2 * C_ + c)   * B_ + b] = skew;
        g_statsT[(3 * C_ + c)   * B_ + b] = kurt;
    }
}

// ---------------- gemm1: h partials = W1 . statsT, K-split 16 ---------------
// W1 tile loaded into registers BEFORE cudaGridDependencySynchronize (PDL).
__global__ __launch_bounds__(256) void gemm1_kernel(const float* __restrict__ W1)
{
    constexpr int KC = 128;
    __shared__ __align__(16) float sA[32 * KC];   // [jj][k] row-major
    __shared__ __align__(16) float sX[KC * 32];   // [k][b]
    const int j0 = blockIdx.x * 32;
    const int i0 = blockIdx.y * KC;
    const int tid = threadIdx.x;

    constexpr int NF = KC / 32;
    float4 va[NF];
    #pragma unroll
    for (int t = 0; t < NF; t++) {
        int f  = tid + t * 256;
        int jj = f / (KC / 4);
        int kq = f % (KC / 4);
        va[t] = *reinterpret_cast<const float4*>(W1 + (size_t)(j0 + jj) * H4C + i0 + 4 * kq);
    }

    cudaGridDependencySynchronize();       // statsT now visible

    {
        float4 vx[NF];
        const float4* x4 = reinterpret_cast<const float4*>(g_statsT + (size_t)i0 * B_);
        #pragma unroll
        for (int t = 0; t < NF; t++)
            vx[t] = x4[tid + t * 256];
        #pragma unroll
        for (int t = 0; t < NF; t++)
            reinterpret_cast<float4*>(sX)[tid + t * 256] = vx[t];
    }
    #pragma unroll
    for (int t = 0; t < NF; t++)
        reinterpret_cast<float4*>(sA)[tid + t * 256] = va[t];
    __syncthreads();

    const int b  = tid & 31;
    const int jb = (tid >> 5) * 4;
    float a0 = 0.f, a1 = 0.f, a2 = 0.f, a3 = 0.f;
    #pragma unroll 8
    for (int k4 = 0; k4 < KC / 4; k4++) {
        float4 r0 = reinterpret_cast<const float4*>(sA)[(jb + 0) * (KC / 4) + k4];
        float4 r1 = reinterpret_cast<const float4*>(sA)[(jb + 1) * (KC / 4) + k4];
        float4 r2 = reinterpret_cast<const float4*>(sA)[(jb + 2) * (KC / 4) + k4];
        float4 r3 = reinterpret_cast<const float4*>(sA)[(jb + 3) * (KC / 4) + k4];
        float s0 = sX[(4 * k4 + 0) * 32 + b];
        float s1 = sX[(4 * k4 + 1) * 32 + b];
        float s2 = sX[(4 * k4 + 2) * 32 + b];
        float s3 = sX[(4 * k4 + 3) * 32 + b];
        a0 = fmaf(r0.x, s0, a0); a0 = fmaf(r0.y, s1, a0); a0 = fmaf(r0.z, s2, a0); a0 = fmaf(r0.w, s3, a0);
        a1 = fmaf(r1.x, s0, a1); a1 = fmaf(r1.y, s1, a1); a1 = fmaf(r1.z, s2, a1); a1 = fmaf(r1.w, s3, a1);
        a2 = fmaf(r2.x, s0, a2); a2 = fmaf(r2.y, s1, a2); a2 = fmaf(r2.z, s2, a2); a2 = fmaf(r2.w, s3, a2);
        a3 = fmaf(r3.x, s0, a3); a3 = fmaf(r3.y, s1, a3); a3 = fmaf(r3.z, s2, a3); a3 = fmaf(r3.w, s3, a3);
    }
    size_t obase = (size_t)blockIdx.y * C_ * B_ + (size_t)(j0 + jb) * B_ + b;
    g_p1[obase + 0 * B_] = a0;
    g_p1[obase + 1 * B_] = a1;
    g_p1[obase + 2 * B_] = a2;
    g_p1[obase + 3 * B_] = a3;
}

// ---------------- reduce1: 16-way partial sum + bias -> hT (both layouts) ---
__global__ __launch_bounds__(256) void reduce1_kernel(const float* __restrict__ b1)
{
    int idx4 = blockIdx.x * 256 + threadIdx.x;    // over C_*B_/4 = 4096 float4s
    int r  = idx4 >> 3;                           // hidden index
    int bq = idx4 & 7;                            // batch quad
    float bv = (idx4 < C_ * B_ / 4) ? b1[r] : 0.f;
    cudaGridDependencySynchronize();
    if (idx4 >= C_ * B_ / 4) return;
    float4 acc = make_float4(bv, bv, bv, bv);
    #pragma unroll
    for (int sp = 0; sp < SP1; sp++) {
        float4 p = reinterpret_cast<const float4*>(g_p1)[sp * (C_ * B_ / 4) + idx4];
        acc.x += p.x; acc.y += p.y; acc.z += p.z; acc.w += p.w;
    }
    reinterpret_cast<float4*>(g_hT)[idx4] = acc;
    // transposed copy (batch-major) for the apply kernel's coalesced gate dot
    int b0 = bq * 4;
    g_hTt[(b0 + 0) * C_ + r] = acc.x;
    g_hTt[(b0 + 1) * C_ + r] = acc.y;
    g_hTt[(b0 + 2) * C_ + r] = acc.z;
    g_hTt[(b0 + 3) * C_ + r] = acc.w;
}

// ---------------- apply: in-block gate GEMV + softmax + weighted combine ----
// gemm2 is eliminated: each block computes its two 512-long gate dot products
// from L2-hot hTt/W2 (fixed-order reduction -> deterministic), fully hidden
// under its own front-batched xa/xb DRAM loads.
__global__ __launch_bounds__(256) void apply_kernel(
    const float* __restrict__ xa, const float* __restrict__ xb,
    const float* __restrict__ W2, const float* __restrict__ b2,
    float* __restrict__ out)
{
    int lin = (B_ * C_ - 1) - (int)(blockIdx.y * C_ + blockIdx.x);
    int b = lin / C_;
    int c = lin - b * C_;
    const int tid = threadIdx.x;

    // ---- pre-sync: pure inputs (W2 rows + bias) ----
    float w00 = W2[(size_t)(0 * C_ + c) * C_ + tid];
    float w01 = W2[(size_t)(0 * C_ + c) * C_ + tid + 256];
    float w10 = W2[(size_t)(1 * C_ + c) * C_ + tid];
    float w11 = W2[(size_t)(1 * C_ + c) * C_ + tid + 256];
    float bias0 = b2[c];
    float bias1 = b2[C_ + c];

    cudaGridDependencySynchronize();       // g_hTt now visible

    // h values for this batch (coalesced)
    float h0 = g_hTt[b * C_ + tid];
    float h1 = g_hTt[b * C_ + tid + 256];

    // issue the big streaming loads NOW; gate math hides under their latency
    size_t base = ((size_t)(b * C_ + c)) * T_;
    const float4* a4 = reinterpret_cast<const float4*>(xa + base);
    const float4* b4 = reinterpret_cast<const float4*>(xb + base);
    float4* o4 = reinterpret_cast<float4*>(out + base);
    float4 av[4], bv[4];
    av[0] = a4[tid];        bv[0] = b4[tid];
    av[1] = a4[tid + 256];  bv[1] = b4[tid + 256];
    av[2] = a4[tid + 512];  bv[2] = b4[tid + 512];
    bool p3 = tid < (NV_ - 768);
    if (p3) { av[3] = a4[tid + 768]; bv[3] = b4[tid + 768]; }

    // gate dot products (each thread: 2 k-values per branch)
    float p0 = fmaf(h0, w00, h1 * w01);
    float p1 = fmaf(h0, w10, h1 * w11);
    #pragma unroll
    for (int off = 16; off > 0; off >>= 1) {
        p0 += __shfl_down_sync(0xffffffffu, p0, off);
        p1 += __shfl_down_sync(0xffffffffu, p1, off);
    }
    __shared__ float sred[8][2];
    __shared__ float sg[2];
    int w = tid >> 5;
    if ((tid & 31) == 0) { sred[w][0] = p0; sred[w][1] = p1; }
    __syncthreads();
    if (tid == 0) {
        float s0 = bias0, s1 = bias1;
        #pragma unroll
        for (int i = 0; i < 8; i++) { s0 += sred[i][0]; s1 += sred[i][1]; }
        float mx = fmaxf(s0, s1);
        float e0 = __expf(s0 - mx);
        float e1 = __expf(s1 - mx);
        float inv = 1.f / (e0 + e1);
        sg[0] = e0 * inv;
        sg[1] = e1 * inv;
    }
    __syncthreads();
    float g0 = sg[0];
    float g1 = sg[1];

    float4 r[4];
    #pragma unroll
    for (int t = 0; t < 4; t++) {
        r[t].x = fmaf(av[t].x, g0, bv[t].x * g1);
        r[t].y = fmaf(av[t].y, g0, bv[t].y * g1);
        r[t].z = fmaf(av[t].z, g0, bv[t].z * g1);
        r[t].w = fmaf(av[t].w, g0, bv[t].w * g1);
    }
    __stcs(&o4[tid],       r[0]);
    __stcs(&o4[tid + 256], r[1]);
    __stcs(&o4[tid + 512], r[2]);
    if (p3) __stcs(&o4[tid + 768], r[3]);
}

// ---------------- launcher --------------------------------------------------
static inline void launch_pdl(const void* fn, dim3 grid, dim3 block,
                              void** args)
{
    cudaLaunchConfig_t cfg = {};
    cfg.gridDim  = grid;
    cfg.blockDim = block;
    cfg.dynamicSmemBytes = 0;
    cfg.stream = 0;
    cudaLaunchAttribute attr[1];
    attr[0].id = cudaLaunchAttributeProgrammaticStreamSerialization;
    attr[0].val.programmaticStreamSerializationAllowed = 1;
    cfg.attrs = attr;
    cfg.numAttrs = 1;
    cudaLaunchKernelExC(&cfg, fn, args);
}

extern "C" void kernel_launch(void* const* d_in, const int* in_sizes, int n_in,
                              void* d_out, int out_size)
{
    const float* xa = (const float*)d_in[0];
    const float* xb = (const float*)d_in[1];
    const float* W1 = (const float*)d_in[2];
    const float* b1 = (const float*)d_in[3];
    const float* W2 = (const float*)d_in[4];
    const float* b2 = (const float*)d_in[5];
    float* out = (float*)d_out;

    stats_kernel<<<dim3(C_, B_), 256>>>(xa, xb);

    {   // gemm1: PDL secondary of stats (W1 preload overlaps stats tail)
        void* args[] = { (void*)&W1 };
        launch_pdl((const void*)gemm1_kernel, dim3(C_ / 32, SP1), dim3(256), args);
    }
    {   // reduce1: PDL secondary of gemm1 (writes hT in both layouts)
        void* args[] = { (void*)&b1 };
        launch_pdl((const void*)reduce1_kernel, dim3(C_ * B_ / 4 / 256), dim3(256), args);
    }
    {   // apply: PDL secondary of reduce1; computes gates in-block (no gemm2)
        void* args[] = { (void*)&xa, (void*)&xb, (void*)&W2, (void*)&b2, (void*)&out };
        launch_pdl((const void*)apply_kernel, dim3(C_, B_), dim3(256), args);
    }
}